// round 8
// baseline (speedup 1.0000x reference)
#include <cuda_runtime.h>

// Shapes fixed by the problem's setup_inputs().
#define B_  8
#define H_  16
#define NT_ 512
#define NV_ 576

#define EPS_MIN 1e-8f
#define EPS_MAX 1.0f

// Per-layer diagonal accumulators (atomic float adds).
// Zero-initialized at module load; finalize_kernel re-zeroes each element
// right after consuming it, so every kernel_launch call starts from zeros.
__device__ float g_tdiag[2 * B_ * NT_];   // 8192 floats = 32 * 256
__device__ float g_vdiag[2 * B_ * NV_];   // 9216 floats = 36 * 256

// One block (256 threads) = 32(i) x 64(j) tile for one (layer, b).
//   thread t: p = t & 7 (float4 slot), q = t >> 3 (row index 0..31)
//   attn_t: (i = i0+q, j = j0+4p..+3) and (i = i0+q, j = j0+32+4p..+3)
//   attn_v: (j = j0+q, i = i0+4p..+3) and (j = j0+32+q, i = i0+4p..+3)
// All loads are float4 along each tensor's contiguous dim -> coalesced.
// prod[i][j] = P_t_sum[i][j] * P_v_sum[j][i]; row sums -> g_tdiag,
// column sums -> g_vdiag.
__global__ __launch_bounds__(256)
void diag_kernel(const float* __restrict__ at0, const float* __restrict__ av0,
                 const float* __restrict__ at1, const float* __restrict__ av1,
                 float* __restrict__ out) {
    __shared__ float shV[64][33];   // P_v sums: shV[j-j0][i-i0] (stride-33)
    __shared__ float shP[64][33];   // prod tile: shP[j-j0][i-i0]

    const int t = threadIdx.x;
    const int p = t & 7;            // float4 slot within 32-col half
    const int q = t >> 3;           // row (i for attn_t, j for attn_v)

    const int z     = blockIdx.z;
    const int layer = z >> 3;
    const int b     = z & 7;
    const int i0    = blockIdx.y * 32;
    const int j0    = blockIdx.x * 64;

    // Initialize the (poisoned) output once; ordered before finalize_kernel
    // by the kernel launch boundary.
    if (z == 0 && blockIdx.y == 0 && blockIdx.x == 0 && t == 0)
        out[0] = 0.0f;

    const float* __restrict__ at = layer ? at1 : at0;
    const float* __restrict__ av = layer ? av1 : av0;

    // Base pointers at h = 0; head stride in float4 units.
    const size_t hstride4 = (size_t)NT_ * NV_ / 4;   // 73728
    const float4* __restrict__ pta = (const float4*)(
        at + (((size_t)b * H_) * NT_ + (i0 + q)) * NV_ + (j0 + 4 * p));
    const float4* __restrict__ ptb = pta + 8;   // +32 floats along j
    const float4* __restrict__ pva = (const float4*)(
        av + (((size_t)b * H_) * NV_ + (j0 + q)) * NT_ + (i0 + 4 * p));
    const float4* __restrict__ pvb = pva + 8 * NT_ / 4 * 4 / 4;  // +32 j-rows
    // (j + 32) row offset = 32 * NT_ floats = 8 * NT_ float4s
    pvb = pva + 8 * NT_;

    float4 sta = make_float4(0.f, 0.f, 0.f, 0.f);
    float4 stb = make_float4(0.f, 0.f, 0.f, 0.f);
    float4 sva = make_float4(0.f, 0.f, 0.f, 0.f);
    float4 svb = make_float4(0.f, 0.f, 0.f, 0.f);
#pragma unroll
    for (int h = 0; h < H_; ++h) {
        const float4 a0 = pta[h * hstride4];
        const float4 a1 = ptb[h * hstride4];
        const float4 v0 = pva[h * hstride4];
        const float4 v1 = pvb[h * hstride4];
        sta.x += a0.x; sta.y += a0.y; sta.z += a0.z; sta.w += a0.w;
        stb.x += a1.x; stb.y += a1.y; stb.z += a1.z; stb.w += a1.w;
        sva.x += v0.x; sva.y += v0.y; sva.z += v0.z; sva.w += v0.w;
        svb.x += v1.x; svb.y += v1.y; svb.z += v1.z; svb.w += v1.w;
    }

    // Stage P_v sums: shV[j - j0][i - i0]
    shV[q][4 * p + 0]      = sva.x;
    shV[q][4 * p + 1]      = sva.y;
    shV[q][4 * p + 2]      = sva.z;
    shV[q][4 * p + 3]      = sva.w;
    shV[32 + q][4 * p + 0] = svb.x;
    shV[32 + q][4 * p + 1] = svb.y;
    shV[32 + q][4 * p + 2] = svb.z;
    shV[32 + q][4 * p + 3] = svb.w;
    __syncthreads();

    // prod for (i = i0+q, j = j0+{4p+c, 32+4p+c}); shV reads conflict-free:
    // addr mod 32 = (4p+c+q), bijective over the warp for fixed c.
    const float pa0 = sta.x * shV[4 * p + 0][q];
    const float pa1 = sta.y * shV[4 * p + 1][q];
    const float pa2 = sta.z * shV[4 * p + 2][q];
    const float pa3 = sta.w * shV[4 * p + 3][q];
    const float pb0 = stb.x * shV[32 + 4 * p + 0][q];
    const float pb1 = stb.y * shV[32 + 4 * p + 1][q];
    const float pb2 = stb.z * shV[32 + 4 * p + 2][q];
    const float pb3 = stb.w * shV[32 + 4 * p + 3][q];

    // Row sum over all 64 j: reduce 8 values then across p (8 threads).
    float rs = ((pa0 + pa1) + (pa2 + pa3)) + ((pb0 + pb1) + (pb2 + pb3));
    rs += __shfl_xor_sync(0xffffffffu, rs, 1);
    rs += __shfl_xor_sync(0xffffffffu, rs, 2);
    rs += __shfl_xor_sync(0xffffffffu, rs, 4);
    if (p == 0)
        atomicAdd(&g_tdiag[layer * (B_ * NT_) + b * NT_ + i0 + q], rs);

    // Column sums: stage prod tile, then read by column.
    shP[4 * p + 0][q]      = pa0;
    shP[4 * p + 1][q]      = pa1;
    shP[4 * p + 2][q]      = pa2;
    shP[4 * p + 3][q]      = pa3;
    shP[32 + 4 * p + 0][q] = pb0;
    shP[32 + 4 * p + 1][q] = pb1;
    shP[32 + 4 * p + 2][q] = pb2;
    shP[32 + 4 * p + 3][q] = pb3;
    __syncthreads();

    // Thread handles columns j = j0+q and j = j0+32+q, rows i = 4p+c.
    // Reads shP[q][4p+c]: addr mod 32 = q+4p+c -> conflict-free.
    float csa = shP[q][4 * p + 0] + shP[q][4 * p + 1]
              + shP[q][4 * p + 2] + shP[q][4 * p + 3];
    float csb = shP[32 + q][4 * p + 0] + shP[32 + q][4 * p + 1]
              + shP[32 + q][4 * p + 2] + shP[32 + q][4 * p + 3];
    csa += __shfl_xor_sync(0xffffffffu, csa, 1);
    csa += __shfl_xor_sync(0xffffffffu, csa, 2);
    csa += __shfl_xor_sync(0xffffffffu, csa, 4);
    csb += __shfl_xor_sync(0xffffffffu, csb, 1);
    csb += __shfl_xor_sync(0xffffffffu, csb, 2);
    csb += __shfl_xor_sync(0xffffffffu, csb, 4);
    if (p == 0) {
        atomicAdd(&g_vdiag[layer * (B_ * NV_) + b * NV_ + j0 + q], csa);
        atomicAdd(&g_vdiag[layer * (B_ * NV_) + b * NV_ + j0 + 32 + q], csb);
    }
}

// Finalize: exactly one diag element per thread.
//   blocks [0, 32)  -> g_tdiag (32*256 = 8192 elements)
//   blocks [32, 68) -> g_vdiag (36*256 = 9216 elements)
// Each thread: load (L2-coherent), re-zero, clip, -log, pre-scale; block
// reduce; one atomicAdd into out[0] per block. The kernel boundary orders
// all diag atomics before us.
__global__ __launch_bounds__(256)
void finalize_kernel(float* __restrict__ out) {
    __shared__ float red[8];
    const int t   = threadIdx.x;
    const int blk = blockIdx.x;
    const float inv_h2 = 1.0f / (float)(H_ * H_);  // sums -> products of means

    float scale, d;
    if (blk < 32) {
        const int idx = blk * 256 + t;
        d = __ldcg(&g_tdiag[idx]) * inv_h2;
        __stcg(&g_tdiag[idx], 0.0f);               // reset for next replay
        scale = 0.25f / (float)(B_ * NT_);
    } else {
        const int idx = (blk - 32) * 256 + t;
        d = __ldcg(&g_vdiag[idx]) * inv_h2;
        __stcg(&g_vdiag[idx], 0.0f);
        scale = 0.25f / (float)(B_ * NV_);
    }
    d = fminf(fmaxf(d, EPS_MIN), EPS_MAX);
    float acc = -__logf(d) * scale;

#pragma unroll
    for (int o = 16; o > 0; o >>= 1)
        acc += __shfl_xor_sync(0xffffffffu, acc, o);
    const int w = t >> 5, l = t & 31;
    if (l == 0) red[w] = acc;
    __syncthreads();
    if (t == 0) {
        float s = 0.0f;
#pragma unroll
        for (int k = 0; k < 8; ++k) s += red[k];
        atomicAdd(out, s);
    }
}

extern "C" void kernel_launch(void* const* d_in, const int* in_sizes, int n_in,
                              void* d_out, int out_size) {
    const float* at0 = (const float*)d_in[0];
    const float* av0 = (const float*)d_in[1];
    const float* at1 = (const float*)d_in[2];
    const float* av1 = (const float*)d_in[3];

    // Fused head-mean + diagonal row/col sums (also zeroes out[0]).
    // grid: x = NV/64 = 9 j-tiles, y = NT/32 = 16 i-tiles, z = layer*8 + b
    dim3 grid(NV_ / 64, NT_ / 32, 2 * B_);
    diag_kernel<<<grid, 256>>>(at0, av0, at1, av1, (float*)d_out);

    // One element per thread; one atomicAdd into out[0] per block.
    finalize_kernel<<<68, 256>>>((float*)d_out);
}

// round 9
// speedup vs baseline: 1.0217x; 1.0217x over previous
#include <cuda_runtime.h>

// Shapes fixed by the problem's setup_inputs().
#define B_  8
#define H_  16
#define NT_ 512
#define NV_ 576

#define EPS_MIN 1e-8f
#define EPS_MAX 1.0f

// Per-layer diagonal accumulators (atomic float adds).
// Zero-initialized at module load; finalize_kernel re-zeroes each element
// right after consuming it, so every kernel_launch call starts from zeros.
__device__ float g_tdiag[2 * B_ * NT_];   // 8192 floats = 32 * 256
__device__ float g_vdiag[2 * B_ * NV_];   // 9216 floats = 36 * 256

// One block (256 threads) = 32(i) x 32(j) tile for one (layer, b).
//   thread t: p = t & 7 (float4 slot), q = t >> 3 (row index 0..31)
//   attn_t: element (i = i0+q, j = j0+4p..+3)  -> float4 along j (contiguous)
//   attn_v: element (j = j0+q, i = i0+4p..+3)  -> float4 along i (contiguous)
// prod[i][j] = P_t_sum[i][j] * P_v_sum[j][i]; row sums -> g_tdiag,
// column sums -> g_vdiag. minBlocksPerMultiprocessor=8 caps regs at 32 so
// 8 CTAs stay resident: 4608 blocks / 1184 concurrent = 3.89 waves with an
// 89%-full tail (vs 4.45 waves / 45% tail at 7 CTAs).
__global__ __launch_bounds__(256, 8)
void diag_kernel(const float* __restrict__ at0, const float* __restrict__ av0,
                 const float* __restrict__ at1, const float* __restrict__ av1,
                 float* __restrict__ out) {
    __shared__ float shV[32][33];   // P_v sums, stride-33 -> conflict-free transpose
    __shared__ float shP[32][33];   // prod tile for column reduction

    const int t = threadIdx.x;
    const int p = t & 7;            // float4 slot within row
    const int q = t >> 3;           // row (i for attn_t, j for attn_v)

    const int z     = blockIdx.z;
    const int layer = z >> 3;
    const int b     = z & 7;
    const int i0    = blockIdx.y * 32;
    const int j0    = blockIdx.x * 32;

    // Initialize the (poisoned) output once; ordered before finalize_kernel
    // by the kernel launch boundary.
    if (z == 0 && blockIdx.y == 0 && blockIdx.x == 0 && t == 0)
        out[0] = 0.0f;

    const float* __restrict__ at = layer ? at1 : at0;
    const float* __restrict__ av = layer ? av1 : av0;

    // Base pointers at h = 0; head stride in float4 units.
    const size_t hstride4 = (size_t)NT_ * NV_ / 4;   // 73728
    const float4* __restrict__ pt = (const float4*)(
        at + (((size_t)b * H_) * NT_ + (i0 + q)) * NV_ + (j0 + 4 * p));
    const float4* __restrict__ pv = (const float4*)(
        av + (((size_t)b * H_) * NV_ + (j0 + q)) * NT_ + (i0 + 4 * p));

    float4 st = make_float4(0.f, 0.f, 0.f, 0.f);
    float4 sv = make_float4(0.f, 0.f, 0.f, 0.f);
#pragma unroll
    for (int h = 0; h < H_; ++h) {
        const float4 a = pt[h * hstride4];
        const float4 v = pv[h * hstride4];
        st.x += a.x; st.y += a.y; st.z += a.z; st.w += a.w;
        sv.x += v.x; sv.y += v.y; sv.z += v.z; sv.w += v.w;
    }

    // Stage P_v sums: shV[j - j0][i - i0]
    shV[q][4 * p + 0] = sv.x;
    shV[q][4 * p + 1] = sv.y;
    shV[q][4 * p + 2] = sv.z;
    shV[q][4 * p + 3] = sv.w;
    __syncthreads();

    // prod for (i = i0+q, j = j0+4p+c): needs shV[4p+c][q] (conflict-free).
    const float pr0 = st.x * shV[4 * p + 0][q];
    const float pr1 = st.y * shV[4 * p + 1][q];
    const float pr2 = st.z * shV[4 * p + 2][q];
    const float pr3 = st.w * shV[4 * p + 3][q];

    // Row sum over j: reduce the 8 threads (p = 0..7) sharing row q.
    float rs = (pr0 + pr1) + (pr2 + pr3);
    rs += __shfl_xor_sync(0xffffffffu, rs, 1);
    rs += __shfl_xor_sync(0xffffffffu, rs, 2);
    rs += __shfl_xor_sync(0xffffffffu, rs, 4);
    if (p == 0)
        atomicAdd(&g_tdiag[layer * (B_ * NT_) + b * NT_ + i0 + q], rs);

    // Column sums: stage prod tile, then read transposed.
    shP[q][4 * p + 0] = pr0;
    shP[q][4 * p + 1] = pr1;
    shP[q][4 * p + 2] = pr2;
    shP[q][4 * p + 3] = pr3;
    __syncthreads();

    // Thread handles column j = j0+q, rows i = 4p+c (conflict-free reads).
    float cs = shP[4 * p + 0][q] + shP[4 * p + 1][q]
             + shP[4 * p + 2][q] + shP[4 * p + 3][q];
    cs += __shfl_xor_sync(0xffffffffu, cs, 1);
    cs += __shfl_xor_sync(0xffffffffu, cs, 2);
    cs += __shfl_xor_sync(0xffffffffu, cs, 4);
    if (p == 0)
        atomicAdd(&g_vdiag[layer * (B_ * NV_) + b * NV_ + j0 + q], cs);
}

// Finalize: exactly one diag element per thread.
//   blocks [0, 32)  -> g_tdiag (32*256 = 8192 elements)
//   blocks [32, 68) -> g_vdiag (36*256 = 9216 elements)
// Each thread: load (L2-coherent), re-zero, clip, -log, pre-scale; block
// reduce; one atomicAdd into out[0] per block. The kernel boundary orders
// all diag atomics before us; the harness's stream sync orders our atomics
// before the host reads d_out.
__global__ __launch_bounds__(256)
void finalize_kernel(float* __restrict__ out) {
    __shared__ float red[8];
    const int t   = threadIdx.x;
    const int blk = blockIdx.x;
    const float inv_h2 = 1.0f / (float)(H_ * H_);  // sums -> products of means

    float scale, d;
    if (blk < 32) {
        const int idx = blk * 256 + t;
        d = __ldcg(&g_tdiag[idx]) * inv_h2;
        __stcg(&g_tdiag[idx], 0.0f);               // reset for next replay
        scale = 0.25f / (float)(B_ * NT_);
    } else {
        const int idx = (blk - 32) * 256 + t;
        d = __ldcg(&g_vdiag[idx]) * inv_h2;
        __stcg(&g_vdiag[idx], 0.0f);
        scale = 0.25f / (float)(B_ * NV_);
    }
    d = fminf(fmaxf(d, EPS_MIN), EPS_MAX);
    float acc = -__logf(d) * scale;

#pragma unroll
    for (int o = 16; o > 0; o >>= 1)
        acc += __shfl_xor_sync(0xffffffffu, acc, o);
    const int w = t >> 5, l = t & 31;
    if (l == 0) red[w] = acc;
    __syncthreads();
    if (t == 0) {
        float s = 0.0f;
#pragma unroll
        for (int k = 0; k < 8; ++k) s += red[k];
        atomicAdd(out, s);
    }
}

extern "C" void kernel_launch(void* const* d_in, const int* in_sizes, int n_in,
                              void* d_out, int out_size) {
    const float* at0 = (const float*)d_in[0];
    const float* av0 = (const float*)d_in[1];
    const float* at1 = (const float*)d_in[2];
    const float* av1 = (const float*)d_in[3];

    // Fused head-mean + diagonal row/col sums (also zeroes out[0]).
    // grid: x = NV/32 = 18 j-tiles, y = NT/32 = 16 i-tiles, z = layer*8 + b
    dim3 grid(NV_ / 32, NT_ / 32, 2 * B_);
    diag_kernel<<<grid, 256>>>(at0, av0, at1, av1, (float*)d_out);

    // One element per thread; one atomicAdd into out[0] per block.
    finalize_kernel<<<68, 256>>>((float*)d_out);
}

// round 10
// speedup vs baseline: 1.0284x; 1.0066x over previous
#include <cuda_runtime.h>

// Shapes fixed by the problem's setup_inputs().
#define B_  8
#define H_  16
#define NT_ 512
#define NV_ 576

#define EPS_MIN 1e-8f
#define EPS_MAX 1.0f

// Per-layer diagonal accumulators (atomic float adds).
// Zero-initialized at module load; finalize_kernel re-zeroes each element
// right after consuming it, so every kernel_launch call starts from zeros.
__device__ float g_tdiag[2 * B_ * NT_];   // 8192 floats = 32 * 256
__device__ float g_vdiag[2 * B_ * NV_];   // 9216 floats = 36 * 256

// One block (256 threads) = 32(i) x 32(j) tile for one (layer, b).
//   thread t: p = t & 7 (float4 slot), q = t >> 3 (row index 0..31)
//   attn_t: element (i = i0+q, j = j0+4p..+3)  -> float4 along j (contiguous)
//   attn_v: element (j = j0+q, i = i0+4p..+3)  -> float4 along i (contiguous)
// prod[i][j] = P_t_sum[i][j] * P_v_sum[j][i]; row sums -> g_tdiag,
// column sums -> g_vdiag. This exact configuration (natural 36 regs,
// 7 CTAs/SM) measured 7.05 TB/s = 88% of HBM spec — the best of all
// variants tried; do not perturb the hot loop or its residency.
__global__ __launch_bounds__(256)
void diag_kernel(const float* __restrict__ at0, const float* __restrict__ av0,
                 const float* __restrict__ at1, const float* __restrict__ av1,
                 float* __restrict__ out) {
    __shared__ float shV[32][33];   // P_v sums, stride-33 -> conflict-free transpose
    __shared__ float shP[32][33];   // prod tile for column reduction

    const int t = threadIdx.x;
    const int p = t & 7;            // float4 slot within row
    const int q = t >> 3;           // row (i for attn_t, j for attn_v)

    const int z     = blockIdx.z;
    const int layer = z >> 3;
    const int b     = z & 7;
    const int i0    = blockIdx.y * 32;
    const int j0    = blockIdx.x * 32;

    // Initialize the (poisoned) output once; ordered before finalize_kernel
    // by the kernel launch boundary.
    if (z == 0 && blockIdx.y == 0 && blockIdx.x == 0 && t == 0)
        out[0] = 0.0f;

    const float* __restrict__ at = layer ? at1 : at0;
    const float* __restrict__ av = layer ? av1 : av0;

    // Base pointers at h = 0; head stride in float4 units.
    const size_t hstride4 = (size_t)NT_ * NV_ / 4;   // 73728
    const float4* __restrict__ pt = (const float4*)(
        at + (((size_t)b * H_) * NT_ + (i0 + q)) * NV_ + (j0 + 4 * p));
    const float4* __restrict__ pv = (const float4*)(
        av + (((size_t)b * H_) * NV_ + (j0 + q)) * NT_ + (i0 + 4 * p));

    float4 st = make_float4(0.f, 0.f, 0.f, 0.f);
    float4 sv = make_float4(0.f, 0.f, 0.f, 0.f);
#pragma unroll
    for (int h = 0; h < H_; ++h) {
        const float4 a = pt[h * hstride4];
        const float4 v = pv[h * hstride4];
        st.x += a.x; st.y += a.y; st.z += a.z; st.w += a.w;
        sv.x += v.x; sv.y += v.y; sv.z += v.z; sv.w += v.w;
    }

    // Stage P_v sums: shV[j - j0][i - i0]
    shV[q][4 * p + 0] = sv.x;
    shV[q][4 * p + 1] = sv.y;
    shV[q][4 * p + 2] = sv.z;
    shV[q][4 * p + 3] = sv.w;
    __syncthreads();

    // prod for (i = i0+q, j = j0+4p+c): needs shV[4p+c][q] (conflict-free).
    const float pr0 = st.x * shV[4 * p + 0][q];
    const float pr1 = st.y * shV[4 * p + 1][q];
    const float pr2 = st.z * shV[4 * p + 2][q];
    const float pr3 = st.w * shV[4 * p + 3][q];

    // Row sum over j: reduce the 8 threads (p = 0..7) sharing row q.
    float rs = (pr0 + pr1) + (pr2 + pr3);
    rs += __shfl_xor_sync(0xffffffffu, rs, 1);
    rs += __shfl_xor_sync(0xffffffffu, rs, 2);
    rs += __shfl_xor_sync(0xffffffffu, rs, 4);
    if (p == 0)
        atomicAdd(&g_tdiag[layer * (B_ * NT_) + b * NT_ + i0 + q], rs);

    // Column sums: stage prod tile, then read transposed.
    shP[q][4 * p + 0] = pr0;
    shP[q][4 * p + 1] = pr1;
    shP[q][4 * p + 2] = pr2;
    shP[q][4 * p + 3] = pr3;
    __syncthreads();

    // Thread handles column j = j0+q, rows i = 4p+c (conflict-free reads).
    float cs = shP[4 * p + 0][q] + shP[4 * p + 1][q]
             + shP[4 * p + 2][q] + shP[4 * p + 3][q];
    cs += __shfl_xor_sync(0xffffffffu, cs, 1);
    cs += __shfl_xor_sync(0xffffffffu, cs, 2);
    cs += __shfl_xor_sync(0xffffffffu, cs, 4);
    if (p == 0)
        atomicAdd(&g_vdiag[layer * (B_ * NV_) + b * NV_ + j0 + q], cs);
}

// Finalize: exactly one diag element per thread.
//   blocks [0, 32)  -> g_tdiag (32*256 = 8192 elements)
//   blocks [32, 68) -> g_vdiag (36*256 = 9216 elements)
// Each thread: load (L2-coherent), re-zero, clip, -log, pre-scale; block
// reduce; one atomicAdd into out[0] per block. The kernel boundary orders
// all diag atomics before us; the harness's stream sync orders our atomics
// before the host reads d_out.
__global__ __launch_bounds__(256)
void finalize_kernel(float* __restrict__ out) {
    __shared__ float red[8];
    const int t   = threadIdx.x;
    const int blk = blockIdx.x;
    const float inv_h2 = 1.0f / (float)(H_ * H_);  // sums -> products of means

    float scale, d;
    if (blk < 32) {
        const int idx = blk * 256 + t;
        d = __ldcg(&g_tdiag[idx]) * inv_h2;
        __stcg(&g_tdiag[idx], 0.0f);               // reset for next replay
        scale = 0.25f / (float)(B_ * NT_);
    } else {
        const int idx = (blk - 32) * 256 + t;
        d = __ldcg(&g_vdiag[idx]) * inv_h2;
        __stcg(&g_vdiag[idx], 0.0f);
        scale = 0.25f / (float)(B_ * NV_);
    }
    d = fminf(fmaxf(d, EPS_MIN), EPS_MAX);
    float acc = -__logf(d) * scale;

#pragma unroll
    for (int o = 16; o > 0; o >>= 1)
        acc += __shfl_xor_sync(0xffffffffu, acc, o);
    const int w = t >> 5, l = t & 31;
    if (l == 0) red[w] = acc;
    __syncthreads();
    if (t == 0) {
        float s = 0.0f;
#pragma unroll
        for (int k = 0; k < 8; ++k) s += red[k];
        atomicAdd(out, s);
    }
}

extern "C" void kernel_launch(void* const* d_in, const int* in_sizes, int n_in,
                              void* d_out, int out_size) {
    const float* at0 = (const float*)d_in[0];
    const float* av0 = (const float*)d_in[1];
    const float* at1 = (const float*)d_in[2];
    const float* av1 = (const float*)d_in[3];

    // Fused head-mean + diagonal row/col sums (also zeroes out[0]).
    // grid: x = NV/32 = 18 j-tiles, y = NT/32 = 16 i-tiles, z = layer*8 + b
    dim3 grid(NV_ / 32, NT_ / 32, 2 * B_);
    diag_kernel<<<grid, 256>>>(at0, av0, at1, av1, (float*)d_out);

    // One element per thread; one atomicAdd into out[0] per block.
    finalize_kernel<<<68, 256>>>((float*)d_out);
}